// round 7
// baseline (speedup 1.0000x reference)
#include <cuda_runtime.h>
#include <math.h>
#include <string.h>

#define BB 4
#define SS 2048
#define VV 64
#define DD 1024
#define PP 8
#define HH 42
#define KK 49152
#define EPSF 1e-12f
#define COSEPS 1e-8f
#define SQRT_S 45.254834f   // sqrt(2048)
#define NSC 64              // s-chunks in kavp (32 s each)

typedef unsigned long long ull;

// ---------------- scratch (static device globals; no allocs allowed) ----------------
__device__ float g_w1t[HH * DD];              // w1 transposed [H][D]
__device__ float g_n[PP * BB * SS];           // n values
__device__ float g_wsm[PP * BB * SS];         // softmax weights over s
__device__ float g_avp[PP * BB * NSC * DD];   // a_v partials, [pb][chunk][d] (8MB)
__device__ float g_cos[PP * BB];              // cosine sims
__device__ float g_htab[PP * VV * HH];        // tanh(tables@w1+b1) [512][42]

__device__ __forceinline__ ull fma2(ull a, ull b, ull c) {
    ull d;
    asm("fma.rn.f32x2 %0, %1, %2, %3;" : "=l"(d) : "l"(a), "l"(b), "l"(c));
    return d;
}
__device__ __forceinline__ ull pack2(float lo, float hi) {
    float2 f = make_float2(lo, hi);
    ull u; memcpy(&u, &f, 8); return u;
}
__device__ __forceinline__ float2 unpack2(ull u) {
    float2 f; memcpy(&f, &u, 8); return f;
}

// ---------------- kernel 1: knorm — n[p,b,s] (f32x2 dots); tail: w1 transpose ----------
__global__ __launch_bounds__(256) void knorm(const float* __restrict__ ctx,
                                             const float* __restrict__ lora,
                                             const float* __restrict__ w1) {
    __shared__ float su[PP * DD];
    int t = threadIdx.x, warp = t >> 5, lane = t & 31;
    for (int i = t; i < PP * DD; i += 256) {
        float e = lora[i];
        su[i] = e / fmaxf(2.0f * fabsf(e), EPSF);
    }
    __syncthreads();
    int row = blockIdx.x * 8 + warp;          // 1024 blocks x 8 warps = 8192 rows
    int b = row >> 11, s = row & 2047;
    const float4* x4 = reinterpret_cast<const float4*>(ctx + (size_t)row * DD);
    ull nacc = 0;
    ull dacc[PP];
#pragma unroll
    for (int p = 0; p < PP; p++) dacc[p] = 0;
#pragma unroll
    for (int it = 0; it < 8; it++) {
        int q = lane + it * 32;
        float4 x = x4[q];
        ull xlo = pack2(x.x, x.y), xhi = pack2(x.z, x.w);
        nacc = fma2(xlo, xlo, nacc);
        nacc = fma2(xhi, xhi, nacc);
#pragma unroll
        for (int p = 0; p < PP; p++) {
            float4 u = reinterpret_cast<const float4*>(su + p * DD)[q];
            dacc[p] = fma2(xlo, pack2(u.x, u.y), dacc[p]);
            dacc[p] = fma2(xhi, pack2(u.z, u.w), dacc[p]);
        }
    }
    float2 nf = unpack2(nacc);
    float nrm2 = nf.x + nf.y;
    float dot[PP];
#pragma unroll
    for (int p = 0; p < PP; p++) { float2 df = unpack2(dacc[p]); dot[p] = df.x + df.y; }
#pragma unroll
    for (int o = 16; o; o >>= 1) {
        nrm2 += __shfl_xor_sync(0xffffffffu, nrm2, o);
#pragma unroll
        for (int p = 0; p < PP; p++) dot[p] += __shfl_xor_sync(0xffffffffu, dot[p], o);
    }
    if (lane < PP) {
        float dl = 0.f;
#pragma unroll
        for (int p = 0; p < PP; p++) if (lane == p) dl = dot[p];
        float v = dl / fmaxf(sqrtf(nrm2), EPSF);
        float c = fmaxf(v, 0.f);
        g_n[((size_t)lane * BB + b) * SS + s] = c / fmaxf(SQRT_S * c, EPSF);
    }
    // tail: transpose w1 -> g_w1t  (168*256 = 43008 = D*H exactly)
    if (blockIdx.x < 168) {
        int idx = blockIdx.x * 256 + t;
        int d = idx / HH, h = idx - d * HH;
        g_w1t[(size_t)h * DD + d] = w1[idx];
    }
}

// ---------------- kernel 2: softmax over s (per p,b) -> weights ----------------
__global__ __launch_bounds__(256) void ksoft() {
    __shared__ float sn[SS];
    __shared__ float red[256];
    int pb = blockIdx.x;
    int t = threadIdx.x;
    const float* np = g_n + (size_t)pb * SS;
    float m = -1e30f;
    for (int i = t; i < SS; i += 256) { float v = np[i]; sn[i] = v; m = fmaxf(m, v); }
    red[t] = m; __syncthreads();
    for (int o = 128; o; o >>= 1) { if (t < o) red[t] = fmaxf(red[t], red[t + o]); __syncthreads(); }
    m = red[0]; __syncthreads();
    float sum = 0.f;
    for (int i = t; i < SS; i += 256) sum += expf(sn[i] - m);
    red[t] = sum; __syncthreads();
    for (int o = 128; o; o >>= 1) { if (t < o) red[t] += red[t + o]; __syncthreads(); }
    float inv = 1.0f / red[0];
    for (int i = t; i < SS; i += 256) g_wsm[(size_t)pb * SS + i] = expf(sn[i] - m) * inv;
}

// ---------------- kernel 3: a_v partials (f32x2, duplicated weights) ----------------
// grid (NSC, B): 32 s-rows, all D per block (256 thr x float4).
__global__ __launch_bounds__(256) void kavp(const float* __restrict__ ctx) {
    __shared__ ull ws2[32 * PP];          // weights duplicated {w,w}
    int schunk = blockIdx.x, b = blockIdx.y;
    int t = threadIdx.x;
    {
        int sl = t >> 3, p = t & 7;
        float w = g_wsm[((size_t)p * BB + b) * SS + schunk * 32 + sl];
        ws2[t] = pack2(w, w);
    }
    __syncthreads();
    ull alo[PP], ahi[PP];
#pragma unroll
    for (int p = 0; p < PP; p++) { alo[p] = 0; ahi[p] = 0; }
    const float4* cp = reinterpret_cast<const float4*>(ctx) +
                       ((size_t)b * SS + schunk * 32) * 256 + t;
#pragma unroll
    for (int sl = 0; sl < 32; sl += 8) {
        ull xlo[8], xhi[8];
#pragma unroll
        for (int r = 0; r < 8; r++) {
            float4 x = cp[(size_t)(sl + r) * 256];
            xlo[r] = pack2(x.x, x.y);
            xhi[r] = pack2(x.z, x.w);
        }
#pragma unroll
        for (int p = 0; p < PP; p++) {
#pragma unroll
            for (int r = 0; r < 8; r++) {
                ull wv = ws2[(sl + r) * 8 + p];
                alo[p] = fma2(xlo[r], wv, alo[p]);
                ahi[p] = fma2(xhi[r], wv, ahi[p]);
            }
        }
    }
#pragma unroll
    for (int p = 0; p < PP; p++) {
        float2 lo = unpack2(alo[p]), hi = unpack2(ahi[p]);
        reinterpret_cast<float4*>(g_avp)[((size_t)(p * BB + b) * NSC + schunk) * 256 + t] =
            make_float4(lo.x, lo.y, hi.x, hi.y);
    }
}

// ---------------- kernel 4: kmid2 — cos (blk<32) || htab 4 rows/blk (32<=blk<160) -----
__global__ __launch_bounds__(256) void kmid2(const float* __restrict__ lora,
                                             const float* __restrict__ tables,
                                             const float* __restrict__ b1) {
    int blk = blockIdx.x;
    int t = threadIdx.x, warp = t >> 5, lane = t & 31;
    if (blk < 32) {
        // ---- reduce 64 partial chunks + cosine, all in registers ----
        __shared__ float red3[24];
        int pb = blk, p = pb >> 2;
        const float4* av4 = reinterpret_cast<const float4*>(g_avp) + (size_t)pb * NSC * 256 + t;
        float4 s = make_float4(0.f, 0.f, 0.f, 0.f);
#pragma unroll
        for (int c0 = 0; c0 < NSC; c0 += 16) {
            float4 x[16];
#pragma unroll
            for (int c = 0; c < 16; c++) x[c] = av4[(size_t)(c0 + c) * 256];
#pragma unroll
            for (int c = 0; c < 16; c++) {
                s.x += x[c].x; s.y += x[c].y; s.z += x[c].z; s.w += x[c].w;
            }
        }
        float4 e = reinterpret_cast<const float4*>(lora + (size_t)p * DD)[t];
        float dot = e.x * s.x + e.y * s.y + e.z * s.z + e.w * s.w;
        float an2 = s.x * s.x + s.y * s.y + s.z * s.z + s.w * s.w;
        float en2 = e.x * e.x + e.y * e.y + e.z * e.z + e.w * e.w;
#pragma unroll
        for (int o = 16; o; o >>= 1) {
            dot += __shfl_xor_sync(0xffffffffu, dot, o);
            an2 += __shfl_xor_sync(0xffffffffu, an2, o);
            en2 += __shfl_xor_sync(0xffffffffu, en2, o);
        }
        if (lane == 0) { red3[warp] = dot; red3[8 + warp] = an2; red3[16 + warp] = en2; }
        __syncthreads();
        if (t == 0) {
            float D = 0.f, A = 0.f, E = 0.f;
#pragma unroll
            for (int w = 0; w < 8; w++) { D += red3[w]; A += red3[8 + w]; E += red3[16 + w]; }
            g_cos[pb] = D / fmaxf(sqrtf(E) * sqrtf(A), COSEPS);
        }
    } else {
        // ---- htab: 4 token rows per block, w1t rows feed 16 FMAs each ----
        __shared__ float tok[4 * DD];          // 16 KB
        int quad = blk - 32;                   // 0..127 -> rows quad*4 .. +3
        const float* src = tables + (size_t)quad * 4 * DD;
        for (int i = t; i < 4 * DD; i += 256) tok[i] = src[i];
        __syncthreads();
#pragma unroll
        for (int j = 0; j < 6; j++) {
            int h = warp + j * 8;
            if (h < HH) {
                const float4* wr = reinterpret_cast<const float4*>(g_w1t + (size_t)h * DD);
                float d0 = 0.f, d1 = 0.f, d2 = 0.f, d3 = 0.f;
#pragma unroll
                for (int it = 0; it < 8; it++) {
                    int q = lane + it * 32;
                    float4 wv = wr[q];
                    float4 t0 = reinterpret_cast<const float4*>(tok)[q];
                    float4 t1 = reinterpret_cast<const float4*>(tok + DD)[q];
                    float4 t2 = reinterpret_cast<const float4*>(tok + 2 * DD)[q];
                    float4 t3 = reinterpret_cast<const float4*>(tok + 3 * DD)[q];
                    d0 += wv.x * t0.x + wv.y * t0.y + wv.z * t0.z + wv.w * t0.w;
                    d1 += wv.x * t1.x + wv.y * t1.y + wv.z * t1.z + wv.w * t1.w;
                    d2 += wv.x * t2.x + wv.y * t2.y + wv.z * t2.z + wv.w * t2.w;
                    d3 += wv.x * t3.x + wv.y * t3.y + wv.z * t3.z + wv.w * t3.w;
                }
#pragma unroll
                for (int o = 16; o; o >>= 1) {
                    d0 += __shfl_xor_sync(0xffffffffu, d0, o);
                    d1 += __shfl_xor_sync(0xffffffffu, d1, o);
                    d2 += __shfl_xor_sync(0xffffffffu, d2, o);
                    d3 += __shfl_xor_sync(0xffffffffu, d3, o);
                }
                if (lane == 0) {
                    float bh = b1[h];
                    g_htab[(size_t)(quad * 4 + 0) * HH + h] = tanhf(d0 + bh);
                    g_htab[(size_t)(quad * 4 + 1) * HH + h] = tanhf(d1 + bh);
                    g_htab[(size_t)(quad * 4 + 2) * HH + h] = tanhf(d2 + bh);
                    g_htab[(size_t)(quad * 4 + 3) * HH + h] = tanhf(d3 + bh);
                }
            }
        }
    }
}

// ---------------- kernel 5: kout — gates + hbar inline, then hbar @ w2 + b2 ----------
// 64 rows per block (blockIdx.y of 4), 256 k per block (blockIdx.x of 192). 128 threads.
__global__ __launch_bounds__(128, 4) void kout(const int* __restrict__ prefix,
                                               const float* __restrict__ w2,
                                               const float* __restrict__ b2,
                                               float* __restrict__ out) {
    __shared__ float sgate[32];
    __shared__ ull hb2[64 * HH];   // hbar duplicated {v,v}, [row][h]
    int r0 = blockIdx.y * 64;
    int t = threadIdx.x;
    if (t < 32) {
        int bq = t >> 3, p = t & 7;
        float x[PP], m = -1e30f;
#pragma unroll
        for (int pp = 0; pp < PP; pp++) { x[pp] = g_cos[pp * BB + bq]; m = fmaxf(m, x[pp]); }
        float z = 0.f;
#pragma unroll
        for (int pp = 0; pp < PP; pp++) { x[pp] = expf(x[pp] - m); z += x[pp]; }
#pragma unroll
        for (int pp = 0; pp < PP; pp++) x[pp] /= z;        // s_t
        m = -1e30f;
#pragma unroll
        for (int pp = 0; pp < PP; pp++) m = fmaxf(m, x[pp]);
        z = 0.f;
#pragma unroll
        for (int pp = 0; pp < PP; pp++) { x[pp] = expf(x[pp] - m); z += x[pp]; }
        sgate[t] = x[p] / z;                                // gate[bq][p]
    }
    __syncthreads();
    for (int i = t; i < 64 * HH; i += 128) {
        int r = i / HH, h = i - r * HH;
        int bv = r0 + r;
        int pf = prefix[bv];
        int bq = bv >> 6;
        float s = 0.f;
#pragma unroll
        for (int p = 0; p < PP; p++)
            s += sgate[bq * 8 + p] * g_htab[((size_t)p * VV + pf) * HH + h];
        hb2[i] = pack2(s, s);
    }
    __syncthreads();
    int kp = blockIdx.x * 256 + t * 2;
    ull wcol[HH];
#pragma unroll
    for (int h = 0; h < HH; h++) {
        float2 wv = *reinterpret_cast<const float2*>(w2 + (size_t)h * KK + kp);
        wcol[h] = pack2(wv.x, wv.y);
    }
    float2 bv2 = *reinterpret_cast<const float2*>(b2 + kp);
    ull binit = pack2(bv2.x, bv2.y);
    for (int rg = 0; rg < 64; rg += 4) {
        ull a0 = binit, a1 = binit, a2 = binit, a3 = binit;
#pragma unroll
        for (int h = 0; h < HH; h++) {
            a0 = fma2(wcol[h], hb2[(rg + 0) * HH + h], a0);
            a1 = fma2(wcol[h], hb2[(rg + 1) * HH + h], a1);
            a2 = fma2(wcol[h], hb2[(rg + 2) * HH + h], a2);
            a3 = fma2(wcol[h], hb2[(rg + 3) * HH + h], a3);
        }
        *reinterpret_cast<float2*>(out + (size_t)(r0 + rg + 0) * KK + kp) = unpack2(a0);
        *reinterpret_cast<float2*>(out + (size_t)(r0 + rg + 1) * KK + kp) = unpack2(a1);
        *reinterpret_cast<float2*>(out + (size_t)(r0 + rg + 2) * KK + kp) = unpack2(a2);
        *reinterpret_cast<float2*>(out + (size_t)(r0 + rg + 3) * KK + kp) = unpack2(a3);
    }
}

// ---------------- launcher ----------------
extern "C" void kernel_launch(void* const* d_in, const int* in_sizes, int n_in,
                              void* d_out, int out_size) {
    const int* prefix = nullptr;
    const float *ctx = nullptr, *tables = nullptr, *lora = nullptr;
    const float *w1 = nullptr, *b1 = nullptr, *w2 = nullptr, *b2 = nullptr;
    for (int i = 0; i < n_in; i++) {
        switch (in_sizes[i]) {
            case 256:     prefix = (const int*)d_in[i];   break;  // (B,V) int32
            case 8388608: ctx    = (const float*)d_in[i]; break;  // (B,S,D)
            case 524288:  tables = (const float*)d_in[i]; break;  // (P,V,D)
            case 8192:    lora   = (const float*)d_in[i]; break;  // (P,D)
            case 43008:   w1     = (const float*)d_in[i]; break;  // (D,H)
            case 42:      b1     = (const float*)d_in[i]; break;  // (H,)
            case 2064384: w2     = (const float*)d_in[i]; break;  // (H,K)
            case 49152:   b2     = (const float*)d_in[i]; break;  // (K,)
        }
    }
    float* out = (float*)d_out;

    knorm<<<1024, 256>>>(ctx, lora, w1);
    ksoft<<<32, 256>>>();
    kavp<<<dim3(NSC, 4), 256>>>(ctx);
    kmid2<<<160, 256>>>(lora, tables, b1);
    kout<<<dim3(192, 4), 128>>>(prefix, w2, b2, out);
}